// round 15
// baseline (speedup 1.0000x reference)
#include <cuda_runtime.h>
#include <cuda_bf16.h>
#include <cstdint>

// ---------------------------------------------------------------------------
// Problem constants
// ---------------------------------------------------------------------------
constexpr int BSZ  = 8;
constexpr int NCTX = 4096;
constexpr int MCTX = 300;
constexpr int DM   = 1152;
constexpr int NH   = 16;
constexpr int HD   = 72;           // DM / NH
constexpr int MP   = 320;          // padded M for K^T / V scratch

constexpr size_t XEL  = (size_t)BSZ * NCTX * DM;   // 37,748,736
constexpr size_t WQE  = (size_t)DM * DM;
constexpr size_t WKVE = (size_t)DM * 2 * DM;
constexpr size_t KTE  = (size_t)BSZ * NH * HD * MP;
constexpr size_t VE   = (size_t)BSZ * NH * MP * 80;

// ---------------------------------------------------------------------------
// Scratch (device globals; zero-initialized, no allocations allowed)
// ---------------------------------------------------------------------------
__device__ float g_attn[XEL];                                    // fp32 attn out
__device__ __align__(16) __nv_bfloat16 g_wqh[WQE],  g_wql[WQE];
__device__ __align__(16) __nv_bfloat16 g_wkh[WKVE], g_wkl[WKVE];
__device__ __align__(16) __nv_bfloat16 g_wph[WQE],  g_wpl[WQE];
__device__ __align__(16) __nv_bfloat16 g_qh[XEL],   g_ql[XEL];   // q (scale folded)
__device__ __align__(16) __nv_bfloat16 g_kth[KTE],  g_ktl[KTE];  // K^T [B,H,D,MP]
__device__ __align__(16) __nv_bfloat16 g_vh[VE],    g_vl[VE];    // V   [B,H,MP,80]

// ---------------------------------------------------------------------------
// Helpers
// ---------------------------------------------------------------------------
__device__ __forceinline__ uint32_t smem_u32(const void* p) {
    uint32_t a;
    asm("{ .reg .u64 t; cvta.to.shared.u64 t, %1; cvt.u32.u64 %0, t; }"
        : "=r"(a) : "l"(p));
    return a;
}

__device__ __forceinline__ uint32_t pack_bf2(__nv_bfloat16 a, __nv_bfloat16 b) {
    __nv_bfloat162 t(a, b);
    return *reinterpret_cast<uint32_t*>(&t);
}

__device__ __forceinline__ void split_bf16(float v, __nv_bfloat16& h, __nv_bfloat16& l) {
    h = __float2bfloat16_rn(v);
    l = __float2bfloat16_rn(v - __bfloat162float(h));
}

__device__ __forceinline__ void cp16(uint32_t s, const void* g) {
    asm volatile("cp.async.cg.shared.global [%0], [%1], 16;"
                 :: "r"(s), "l"(g) : "memory");
}
#define CP_COMMIT()   asm volatile("cp.async.commit_group;" ::: "memory")
#define CP_WAIT(N)    asm volatile("cp.async.wait_group %0;" :: "n"(N) : "memory")

__device__ __forceinline__ void ldsm_x4(uint32_t& r0, uint32_t& r1,
                                        uint32_t& r2, uint32_t& r3, uint32_t a) {
    asm volatile("ldmatrix.sync.aligned.m8n8.x4.shared.b16 {%0,%1,%2,%3}, [%4];"
                 : "=r"(r0), "=r"(r1), "=r"(r2), "=r"(r3) : "r"(a));
}

__device__ __forceinline__ void ldsm_x4_t(uint32_t& r0, uint32_t& r1,
                                          uint32_t& r2, uint32_t& r3, uint32_t a) {
    asm volatile("ldmatrix.sync.aligned.m8n8.x4.trans.shared.b16 {%0,%1,%2,%3}, [%4];"
                 : "=r"(r0), "=r"(r1), "=r"(r2), "=r"(r3) : "r"(a));
}

__device__ __forceinline__ void mma16816(float* d, const uint32_t* a,
                                         uint32_t b0, uint32_t b1) {
    asm volatile(
        "mma.sync.aligned.m16n8k16.row.col.f32.bf16.bf16.f32 "
        "{%0,%1,%2,%3}, {%4,%5,%6,%7}, {%8,%9}, {%0,%1,%2,%3};"
        : "+f"(d[0]), "+f"(d[1]), "+f"(d[2]), "+f"(d[3])
        : "r"(a[0]), "r"(a[1]), "r"(a[2]), "r"(a[3]), "r"(b0), "r"(b1));
}

// ---------------------------------------------------------------------------
// Elementwise fp32 -> bf16 hi/lo split (weights only)
// ---------------------------------------------------------------------------
__global__ void split_kernel(const float4* __restrict__ src,
                             uint2* __restrict__ hi, uint2* __restrict__ lo, int n4)
{
    const int i = blockIdx.x * blockDim.x + threadIdx.x;
    if (i >= n4) return;
    float4 v = src[i];
    __nv_bfloat16 h0, h1, h2, h3, l0, l1, l2, l3;
    split_bf16(v.x, h0, l0); split_bf16(v.y, h1, l1);
    split_bf16(v.z, h2, l2); split_bf16(v.w, h3, l3);
    hi[i] = make_uint2(pack_bf2(h0, h1), pack_bf2(h2, h3));
    lo[i] = make_uint2(pack_bf2(l0, l1), pack_bf2(l2, l3));
}

// ---------------------------------------------------------------------------
// GEMM tiling constants (128x128, BK=32, 4 warps of 64x64, 128 thr, occ 2)
// ---------------------------------------------------------------------------
constexpr int AS_STRIDE = 40;
constexpr int BS_STRIDE = 136;
constexpr int A_TILE_B  = 128 * AS_STRIDE * 2;   // 10240
constexpr int B_TILE_B  = 32  * BS_STRIDE * 2;   // 8704
constexpr int OFF_AH = 0;
constexpr int OFF_AL = OFF_AH + A_TILE_B;
constexpr int OFF_BH = OFF_AL + A_TILE_B;
constexpr int OFF_BL = OFF_BH + B_TILE_B;
constexpr int STAGE_B = OFF_BL + B_TILE_B;       // 37888
constexpr int GEMM_SMEM = 2 * STAGE_B;           // 75776

constexpr int KV_BLOCKS = 18 * 19;               // 342
constexpr int Q_BLOCKS  = 9 * 256;               // 2304

__device__ __forceinline__ void produce_B(
    uint32_t st, int k0, int tid, int Nc,
    const __nv_bfloat16* Bgh, const __nv_bfloat16* Bgl)
{
    const int rbase = tid >> 4;
    const int ce    = (tid & 15) * 8;
    #pragma unroll
    for (int pass = 0; pass < 4; ++pass) {
        const int r = rbase + pass * 8;
        const size_t go = (size_t)(k0 + r) * Nc + ce;
        const uint32_t so = (uint32_t)(r * BS_STRIDE + ce) * 2;
        cp16(st + OFF_BH + so, Bgh + go);
        cp16(st + OFF_BL + so, Bgl + go);
    }
    CP_COMMIT();
}

// ---------------------------------------------------------------------------
// GEMM mainloop as a macro-like inline (A fp32 register-prefetch, B cp.async)
// acc must be float[4][8][4]
// ---------------------------------------------------------------------------
struct GemmCtx {
    const float* A;
    const __nv_bfloat16 *Bgh, *Bgl;
    int Mr, Nc, m0;
};

__device__ __forceinline__ void gemm_mainloop(
    const GemmCtx& cx, uint32_t sbase, int tid,
    int aFragRow, int aFragCol, int bFragRow, int bFragCol,
    float acc[4][8][4])
{
    const int arBase = tid >> 3;
    const int acol   = (tid & 7) * 4;
    const int nchunks = DM / 32;

    produce_B(sbase, 0, tid, cx.Nc, cx.Bgh, cx.Bgl);
    {
        char* pAH = (char*)nullptr;
        // stage-0 A convert-store
        extern __shared__ char dsm[];
        pAH = dsm + OFF_AH;
        char* pAL = dsm + OFF_AL;
        #pragma unroll
        for (int it = 0; it < 8; ++it) {
            const int r = arBase + it * 16;
            int arow = cx.m0 + r; if (arow >= cx.Mr) arow = cx.Mr - 1;
            float4 v = *(const float4*)(cx.A + (size_t)arow * DM + acol);
            __nv_bfloat16 h0, h1, h2, h3, l0, l1, l2, l3;
            split_bf16(v.x, h0, l0); split_bf16(v.y, h1, l1);
            split_bf16(v.z, h2, l2); split_bf16(v.w, h3, l3);
            const uint32_t off = (uint32_t)(r * AS_STRIDE + acol) * 2;
            *(uint2*)(pAH + off) = make_uint2(pack_bf2(h0, h1), pack_bf2(h2, h3));
            *(uint2*)(pAL + off) = make_uint2(pack_bf2(l0, l1), pack_bf2(l2, l3));
        }
    }
    CP_WAIT(0);
    __syncthreads();

    extern __shared__ char dsm[];
    for (int c = 0; c < nchunks; ++c) {
        const int cur = c & 1;
        const int nb  = c + 1;
        const bool havenb = nb < nchunks;

        float4 pa[8];
        if (havenb) {
            produce_B(sbase + (nb & 1) * STAGE_B, nb * 32, tid, cx.Nc, cx.Bgh, cx.Bgl);
            const int k0n = nb * 32;
            #pragma unroll
            for (int it = 0; it < 8; ++it) {
                const int r = arBase + it * 16;
                int arow = cx.m0 + r; if (arow >= cx.Mr) arow = cx.Mr - 1;
                pa[it] = *(const float4*)(cx.A + (size_t)arow * DM + k0n + acol);
            }
        }

        const uint32_t st  = sbase + cur * STAGE_B;
        const uint32_t sAH = st + OFF_AH;
        const uint32_t sAL = st + OFF_AL;
        const uint32_t sBH = st + OFF_BH;
        const uint32_t sBL = st + OFF_BL;

        #pragma unroll
        for (int kk = 0; kk < 32; kk += 16) {
            uint32_t Ah[4][4], Bh[4][4];
            #pragma unroll
            for (int mi = 0; mi < 4; ++mi) {
                uint32_t a = sAH + (uint32_t)((aFragRow + mi * 16) * AS_STRIDE
                                              + kk + aFragCol) * 2;
                ldsm_x4(Ah[mi][0], Ah[mi][1], Ah[mi][2], Ah[mi][3], a);
            }
            #pragma unroll
            for (int nj = 0; nj < 4; ++nj) {
                uint32_t boff = (uint32_t)((kk + bFragRow) * BS_STRIDE
                                           + bFragCol + nj * 16) * 2;
                ldsm_x4_t(Bh[nj][0], Bh[nj][1], Bh[nj][2], Bh[nj][3], sBH + boff);
            }
            #pragma unroll
            for (int half = 0; half < 2; ++half) {
                uint32_t Bl[2][4];
                #pragma unroll
                for (int j = 0; j < 2; ++j) {
                    const int nj = half * 2 + j;
                    uint32_t boff = (uint32_t)((kk + bFragRow) * BS_STRIDE
                                               + bFragCol + nj * 16) * 2;
                    ldsm_x4_t(Bl[j][0], Bl[j][1], Bl[j][2], Bl[j][3], sBL + boff);
                }
                #pragma unroll
                for (int mi = 0; mi < 4; ++mi)
                    #pragma unroll
                    for (int f = 0; f < 4; ++f) {
                        const int nf = half * 4 + f;
                        const int nj = nf >> 1, sub = (nf & 1) * 2;
                        mma16816(acc[mi][nf], Ah[mi], Bh[nj][sub], Bh[nj][sub + 1]);
                        mma16816(acc[mi][nf], Ah[mi], Bl[f >> 1][sub], Bl[f >> 1][sub + 1]);
                    }
            }
            uint32_t Al[4][4];
            #pragma unroll
            for (int mi = 0; mi < 4; ++mi) {
                uint32_t a = sAL + (uint32_t)((aFragRow + mi * 16) * AS_STRIDE
                                              + kk + aFragCol) * 2;
                ldsm_x4(Al[mi][0], Al[mi][1], Al[mi][2], Al[mi][3], a);
            }
            #pragma unroll
            for (int mi = 0; mi < 4; ++mi)
                #pragma unroll
                for (int nf = 0; nf < 8; ++nf) {
                    const int nj = nf >> 1, sub = (nf & 1) * 2;
                    mma16816(acc[mi][nf], Al[mi], Bh[nj][sub], Bh[nj][sub + 1]);
                }
        }

        if (havenb) {
            char* pAH = dsm + (nb & 1) * STAGE_B + OFF_AH;
            char* pAL = dsm + (nb & 1) * STAGE_B + OFF_AL;
            #pragma unroll
            for (int it = 0; it < 8; ++it) {
                const int r = arBase + it * 16;
                float4 v = pa[it];
                __nv_bfloat16 h0, h1, h2, h3, l0, l1, l2, l3;
                split_bf16(v.x, h0, l0); split_bf16(v.y, h1, l1);
                split_bf16(v.z, h2, l2); split_bf16(v.w, h3, l3);
                const uint32_t off = (uint32_t)(r * AS_STRIDE + acol) * 2;
                *(uint2*)(pAH + off) = make_uint2(pack_bf2(h0, h1), pack_bf2(h2, h3));
                *(uint2*)(pAL + off) = make_uint2(pack_bf2(l0, l1), pack_bf2(l2, l3));
            }
            CP_WAIT(0);
        }
        __syncthreads();
    }
}

// ---------------------------------------------------------------------------
// Fused Q + KV projection. 1D grid: blocks [0, 342) = KV, [342, 2646) = Q.
// Q epilogue: bf16 hi/lo with softmax scale folded -> g_qh/g_ql.
// KV epilogue: bf16 hi/lo scatter -> g_kth/g_ktl (K^T), g_vh/g_vl (V).
// ---------------------------------------------------------------------------
__global__ __launch_bounds__(128, 2)
void gemm_qkv(const float* __restrict__ x, const float* __restrict__ cond,
              const float* __restrict__ bq, const float* __restrict__ bkv)
{
    extern __shared__ char dsm[];
    const uint32_t sbase = smem_u32(dsm);

    const int tid  = threadIdx.x;
    const int wid  = tid >> 5;
    const int lane = tid & 31;
    const int wm   = wid >> 1;
    const int wn   = wid & 1;

    GemmCtx cx;
    bool isKV;
    const float* bias;
    int n0;
    {
        int bid = blockIdx.x;
        isKV = bid < KV_BLOCKS;
        if (isKV) {
            cx.m0 = (bid / 18) * 128;
            n0    = (bid % 18) * 128;
            cx.A = cond; cx.Bgh = g_wkh + n0; cx.Bgl = g_wkl + n0;
            cx.Mr = BSZ * MCTX; cx.Nc = 2 * DM; bias = bkv;
        } else {
            bid -= KV_BLOCKS;
            cx.m0 = (bid / 9) * 128;
            n0    = (bid % 9) * 128;
            cx.A = x; cx.Bgh = g_wqh + n0; cx.Bgl = g_wql + n0;
            cx.Mr = BSZ * NCTX; cx.Nc = DM; bias = bq;
        }
    }

    const int aFragRow = wm * 64 + (lane & 15);
    const int aFragCol = (lane >> 4) * 8;
    const int bFragRow = lane & 15;
    const int bFragCol = wn * 64 + (lane >> 4) * 8;

    float acc[4][8][4];
    #pragma unroll
    for (int i = 0; i < 4; i++)
        #pragma unroll
        for (int j = 0; j < 8; j++)
            #pragma unroll
            for (int e = 0; e < 4; e++) acc[i][j][e] = 0.0f;

    gemm_mainloop(cx, sbase, tid, aFragRow, aFragCol, bFragRow, bFragCol, acc);

    // ---------------- epilogue ----------------
    const int g = lane >> 2;
    const int t = lane & 3;
    const float qscale = rsqrtf((float)HD);
    #pragma unroll
    for (int mi = 0; mi < 4; ++mi) {
        #pragma unroll
        for (int half = 0; half < 2; ++half) {
            const int row = cx.m0 + wm * 64 + mi * 16 + g + half * 8;
            if (row >= cx.Mr) continue;
            #pragma unroll
            for (int nf = 0; nf < 8; ++nf) {
                const int col = n0 + wn * 64 + nf * 8 + 2 * t;
                float v0 = acc[mi][nf][half * 2 + 0] + bias[col];
                float v1 = acc[mi][nf][half * 2 + 1] + bias[col + 1];
                if (!isKV) {
                    v0 *= qscale; v1 *= qscale;
                    __nv_bfloat16 h0, l0, h1, l1;
                    split_bf16(v0, h0, l0);
                    split_bf16(v1, h1, l1);
                    const size_t off = (size_t)row * DM + col;
                    *(uint32_t*)&g_qh[off] = pack_bf2(h0, h1);
                    *(uint32_t*)&g_ql[off] = pack_bf2(l0, l1);
                } else {
                    const int b = row / MCTX, m = row - b * MCTX;
                    #pragma unroll
                    for (int e = 0; e < 2; ++e) {
                        int c2 = col + e;
                        const float val = e ? v1 : v0;
                        __nv_bfloat16 hh, ll;
                        split_bf16(val, hh, ll);
                        if (c2 < DM) {   // K^T [b,h,d,m]
                            const int h = c2 / HD, d = c2 - h * HD;
                            const size_t off = ((size_t)(b * NH + h) * HD + d) * MP + m;
                            g_kth[off] = hh; g_ktl[off] = ll;
                        } else {         // V [b,h,m,80]
                            c2 -= DM;
                            const int h = c2 / HD, d = c2 - h * HD;
                            const size_t off = ((size_t)(b * NH + h) * MP + m) * 80 + d;
                            g_vh[off] = hh; g_vl[off] = ll;
                        }
                    }
                }
            }
        }
    }
}

// ---------------------------------------------------------------------------
// Output projection: g_attn(fp32) @ wp(split) + bp -> out (fp32)
// ---------------------------------------------------------------------------
__global__ __launch_bounds__(128, 2)
void gemm_o(const float* __restrict__ bias, float* __restrict__ C)
{
    extern __shared__ char dsm[];
    const uint32_t sbase = smem_u32(dsm);

    const int tid  = threadIdx.x;
    const int wid  = tid >> 5;
    const int lane = tid & 31;
    const int n0   = blockIdx.x * 128;
    const int wm   = wid >> 1;
    const int wn   = wid & 1;

    GemmCtx cx;
    cx.m0 = blockIdx.y * 128;
    cx.A  = g_attn;
    cx.Bgh = g_wph + n0; cx.Bgl = g_wpl + n0;
    cx.Mr = BSZ * NCTX; cx.Nc = DM;

    const int aFragRow = wm * 64 + (lane & 15);
    const int aFragCol = (lane >> 4) * 8;
    const int bFragRow = lane & 15;
    const int bFragCol = wn * 64 + (lane >> 4) * 8;

    float acc[4][8][4];
    #pragma unroll
    for (int i = 0; i < 4; i++)
        #pragma unroll
        for (int j = 0; j < 8; j++)
            #pragma unroll
            for (int e = 0; e < 4; e++) acc[i][j][e] = 0.0f;

    gemm_mainloop(cx, sbase, tid, aFragRow, aFragCol, bFragRow, bFragCol, acc);

    const int g = lane >> 2;
    const int t = lane & 3;
    #pragma unroll
    for (int mi = 0; mi < 4; ++mi)
        #pragma unroll
        for (int half = 0; half < 2; ++half) {
            const int row = cx.m0 + wm * 64 + mi * 16 + g + half * 8;
            #pragma unroll
            for (int nf = 0; nf < 8; ++nf) {
                const int col = n0 + wn * 64 + nf * 8 + 2 * t;
                float v0 = acc[mi][nf][half * 2 + 0] + bias[col];
                float v1 = acc[mi][nf][half * 2 + 1] + bias[col + 1];
                *(float2*)(C + (size_t)row * DM + col) = make_float2(v0, v1);
            }
        }
}

// ---------------------------------------------------------------------------
// Tensor-core attention; all operands pre-split bf16 in GMEM, producers are
// pure cp.async. Split-3 on QK^T and P@V. Output fp32 -> g_attn.
// ---------------------------------------------------------------------------
constexpr int QR   = 128;
constexpr int MC   = 64;
constexpr int DP   = 80;
constexpr int QSTR = 88;
constexpr int KSTR = 72;
constexpr int VSTR = 88;
constexpr int OQH = 0;
constexpr int OQL = OQH + QR * QSTR * 2;
constexpr int OKH = OQL + QR * QSTR * 2;
constexpr int OKL = OKH + DP * KSTR * 2;
constexpr int OVH = OKL + DP * KSTR * 2;
constexpr int OVL = OVH + MC * VSTR * 2;
constexpr int ATTN_SMEM = OVL + MC * VSTR * 2;   // 90624

__global__ __launch_bounds__(128, 2)
void attn_tc(const int* __restrict__ mask)
{
    extern __shared__ char dsm[];
    const uint32_t sbase = smem_u32(dsm);

    const int b   = blockIdx.z;
    const int h   = blockIdx.y;
    const int q0  = blockIdx.x * QR;
    const int tid = threadIdx.x;
    const int wid = tid >> 5;
    const int lane = tid & 31;
    const int g   = lane >> 2;
    const int t   = lane & 3;
    const int wq0 = wid * 32;
    const int mv  = mask[b];

    // ---- zero pads once (Q cols 72..79; K rows 72..79) ----
    {
        const uint2 z2 = make_uint2(0u, 0u);
        for (int task = tid; task < QR * 2; task += 128) {
            const int r = task >> 1, half8 = task & 1;
            const uint32_t off = (uint32_t)(r * QSTR + 72 + half8 * 4) * 2;
            *(uint2*)(dsm + OQH + off) = z2;
            *(uint2*)(dsm + OQL + off) = z2;
        }
        for (int task = tid; task < 8 * 9; task += 128) {
            const int d = 72 + task / 9, sg = task % 9;
            if (sg < 9) {
                const uint32_t off = (uint32_t)(d * KSTR + sg * 8) * 2;
                if (sg * 8 < KSTR) {
                    *(uint2*)(dsm + OKH + off) = z2;
                    *(uint2*)(dsm + OKL + off) = z2;
                }
            }
        }
    }

    // ---- Q copy via cp.async ----
    {
        const __nv_bfloat16* qh = g_qh + ((size_t)(b * NCTX) + q0) * DM + h * HD;
        const __nv_bfloat16* ql = g_ql + ((size_t)(b * NCTX) + q0) * DM + h * HD;
        for (int task = tid; task < QR * 9; task += 128) {
            const int r = task / 9, sg = task - r * 9;
            const uint32_t so = (uint32_t)(r * QSTR + sg * 8) * 2;
            cp16(sbase + OQH + so, qh + (size_t)r * DM + sg * 8);
            cp16(sbase + OQL + so, ql + (size_t)r * DM + sg * 8);
        }
        CP_COMMIT();
    }

    float o[2][10][4];
    #pragma unroll
    for (int i = 0; i < 2; i++)
        #pragma unroll
        for (int j = 0; j < 10; j++)
            #pragma unroll
            for (int e = 0; e < 4; e++) o[i][j][e] = 0.0f;
    float rs[4] = {0.f, 0.f, 0.f, 0.f};

    const __nv_bfloat16* kgh = g_kth + (size_t)(b * NH + h) * HD * MP;
    const __nv_bfloat16* kgl = g_ktl + (size_t)(b * NH + h) * HD * MP;
    const __nv_bfloat16* vgh = g_vh + (size_t)(b * NH + h) * MP * 80;
    const __nv_bfloat16* vgl = g_vl + (size_t)(b * NH + h) * MP * 80;

    for (int c0 = 0; c0 < mv; c0 += MC) {
        // ---- K^T copy (72 rows x 64 = 8 x 16B per row) ----
        for (int task = tid; task < HD * 8; task += 128) {
            const int d = task >> 3, sg = task & 7;
            const uint32_t so = (uint32_t)(d * KSTR + sg * 8) * 2;
            cp16(sbase + OKH + so, kgh + (size_t)d * MP + c0 + sg * 8);
            cp16(sbase + OKL + so, kgl + (size_t)d * MP + c0 + sg * 8);
        }
        // ---- V copy (64 rows x 80 = 10 x 16B per row) ----
        for (int task = tid; task < MC * 10; task += 128) {
            const int m = task / 10, sg = task - m * 10;
            const uint32_t so = (uint32_t)(m * VSTR + sg * 8) * 2;
            cp16(sbase + OVH + so, vgh + (size_t)(c0 + m) * 80 + sg * 8);
            cp16(sbase + OVL + so, vgl + (size_t)(c0 + m) * 80 + sg * 8);
        }
        CP_COMMIT();
        CP_WAIT(0);
        __syncthreads();

        // ---- S = Q @ K^T (split-3) ----
        float S[2][8][4];
        #pragma unroll
        for (int i = 0; i < 2; i++)
            #pragma unroll
            for (int j = 0; j < 8; j++)
                #pragma unroll
                for (int e = 0; e < 4; e++) S[i][j][e] = 0.0f;

        #pragma unroll
        for (int kk = 0; kk < 5; ++kk) {
            uint32_t Ah[2][4], Al[2][4];
            #pragma unroll
            for (int mi = 0; mi < 2; ++mi) {
                const uint32_t aoff =
                    (uint32_t)((wq0 + mi * 16 + (lane & 15)) * QSTR
                               + kk * 16 + (lane >> 4) * 8) * 2;
                ldsm_x4(Ah[mi][0], Ah[mi][1], Ah[mi][2], Ah[mi][3], sbase + OQH + aoff);
                ldsm_x4(Al[mi][0], Al[mi][1], Al[mi][2], Al[mi][3], sbase + OQL + aoff);
            }
            #pragma unroll
            for (int nj = 0; nj < 4; ++nj) {
                uint32_t Bh[4], Bl[4];
                const uint32_t boff =
                    (uint32_t)((kk * 16 + (lane & 15)) * KSTR
                               + nj * 16 + (lane >> 4) * 8) * 2;
                ldsm_x4_t(Bh[0], Bh[1], Bh[2], Bh[3], sbase + OKH + boff);
                ldsm_x4_t(Bl[0], Bl[1], Bl[2], Bl[3], sbase + OKL + boff);
                #pragma unroll
                for (int mi = 0; mi < 2; ++mi) {
                    mma16816(S[mi][2 * nj + 0], Ah[mi], Bh[0], Bh[1]);
                    mma16816(S[mi][2 * nj + 1], Ah[mi], Bh[2], Bh[3]);
                    mma16816(S[mi][2 * nj + 0], Ah[mi], Bl[0], Bl[1]);
                    mma16816(S[mi][2 * nj + 1], Ah[mi], Bl[2], Bl[3]);
                    mma16816(S[mi][2 * nj + 0], Al[mi], Bh[0], Bh[1]);
                    mma16816(S[mi][2 * nj + 1], Al[mi], Bh[2], Bh[3]);
                }
            }
        }

        // ---- p = exp(s); accumulate row sums ----
        if (c0 + MC <= mv) {
            #pragma unroll
            for (int mi = 0; mi < 2; ++mi)
                #pragma unroll
                for (int nf = 0; nf < 8; ++nf)
                    #pragma unroll
                    for (int e = 0; e < 4; ++e) {
                        const float p = __expf(S[mi][nf][e]);
                        S[mi][nf][e] = p;
                        rs[mi * 2 + (e >> 1)] += p;
                    }
        } else {
            #pragma unroll
            for (int mi = 0; mi < 2; ++mi)
                #pragma unroll
                for (int nf = 0; nf < 8; ++nf)
                    #pragma unroll
                    for (int e = 0; e < 4; ++e) {
                        const int col = c0 + nf * 8 + 2 * t + (e & 1);
                        const float p = (col < mv) ? __expf(S[mi][nf][e]) : 0.0f;
                        S[mi][nf][e] = p;
                        rs[mi * 2 + (e >> 1)] += p;
                    }
        }

        // ---- O += P @ V (split-3) ----
        #pragma unroll
        for (int kk2 = 0; kk2 < 4; ++kk2) {
            uint32_t Ph[2][4], Pl[2][4];
            #pragma unroll
            for (int mi = 0; mi < 2; ++mi) {
                const int nfa = 2 * kk2, nfb = nfa + 1;
                __nv_bfloat16 hh, ll;
                uint32_t hp[8], lp[8];
                #pragma unroll
                for (int e = 0; e < 4; ++e) {
                    split_bf16(S[mi][nfa][e], hh, ll);
                    hp[e] = (uint32_t)*(uint16_t*)&hh;
                    lp[e] = (uint32_t)*(uint16_t*)&ll;
                    split_bf16(S[mi][nfb][e], hh, ll);
                    hp[4 + e] = (uint32_t)*(uint16_t*)&hh;
                    lp[4 + e] = (uint32_t)*(uint16_t*)&ll;
                }
                Ph[mi][0] = hp[0] | (hp[1] << 16);
                Ph[mi][1] = hp[2] | (hp[3] << 16);
                Ph[mi][2] = hp[4] | (hp[5] << 16);
                Ph[mi][3] = hp[6] | (hp[7] << 16);
                Pl[mi][0] = lp[0] | (lp[1] << 16);
                Pl[mi][1] = lp[2] | (lp[3] << 16);
                Pl[mi][2] = lp[4] | (lp[5] << 16);
                Pl[mi][3] = lp[6] | (lp[7] << 16);
            }
            #pragma unroll
            for (int vt = 0; vt < 5; ++vt) {
                uint32_t Vh[4], Vl[4];
                const uint32_t voff =
                    (uint32_t)((kk2 * 16 + (lane & 15)) * VSTR
                               + vt * 16 + (lane >> 4) * 8) * 2;
                ldsm_x4_t(Vh[0], Vh[1], Vh[2], Vh[3], sbase + OVH + voff);
                ldsm_x4_t(Vl[0], Vl[1], Vl[2], Vl[3], sbase + OVL + voff);
                #pragma unroll
                for (int mi = 0; mi < 2; ++mi) {
                    mma16816(o[mi][2 * vt + 0], Ph[mi], Vh[0], Vh[1]);
                    mma16816(o[mi][2 * vt + 1], Ph[mi], Vh[2], Vh[3]);
                    mma16816(o[mi][2 * vt + 0], Ph[mi], Vl[0], Vl[1]);
                    mma16816(o[mi][2 * vt + 1], Ph[mi], Vl[2], Vl[3]);
                    mma16816(o[mi][2 * vt + 0], Pl[mi], Vh[0], Vh[1]);
                    mma16816(o[mi][2 * vt + 1], Pl[mi], Vh[2], Vh[3]);
                }
            }
        }
        __syncthreads();
    }

    // ---- finalize ----
    #pragma unroll
    for (int i = 0; i < 4; ++i) {
        rs[i] += __shfl_xor_sync(0xFFFFFFFFu, rs[i], 1);
        rs[i] += __shfl_xor_sync(0xFFFFFFFFu, rs[i], 2);
        rs[i] = 1.0f / rs[i];
    }

    float* op = g_attn + (size_t)(b * NCTX) * DM + h * HD;
    #pragma unroll
    for (int mi = 0; mi < 2; ++mi)
        #pragma unroll
        for (int half = 0; half < 2; ++half) {
            const int row = q0 + wq0 + mi * 16 + g + half * 8;
            const float inv = rs[mi * 2 + half];
            #pragma unroll
            for (int nt = 0; nt < 9; ++nt) {
                const int col = nt * 8 + 2 * t;
                float2 v;
                v.x = o[mi][nt][half * 2 + 0] * inv;
                v.y = o[mi][nt][half * 2 + 1] * inv;
                *(float2*)(op + (size_t)row * DM + col) = v;
            }
        }
}

// ---------------------------------------------------------------------------
// Launch
// ---------------------------------------------------------------------------
extern "C" void kernel_launch(void* const* d_in, const int* in_sizes, int n_in,
                              void* d_out, int out_size)
{
    (void)in_sizes; (void)n_in; (void)out_size;
    const float* x    = (const float*)d_in[0];
    const float* cond = (const float*)d_in[1];
    const int*   mask = (const int*)  d_in[2];
    const float* wq   = (const float*)d_in[3];
    const float* bq   = (const float*)d_in[4];
    const float* wkv  = (const float*)d_in[5];
    const float* bkv  = (const float*)d_in[6];
    const float* wp   = (const float*)d_in[7];
    const float* bp   = (const float*)d_in[8];
    float* out        = (float*)d_out;

    __nv_bfloat16 *wqh, *wql, *wkh, *wkl, *wph, *wpl;
    cudaGetSymbolAddress((void**)&wqh, g_wqh); cudaGetSymbolAddress((void**)&wql, g_wql);
    cudaGetSymbolAddress((void**)&wkh, g_wkh); cudaGetSymbolAddress((void**)&wkl, g_wkl);
    cudaGetSymbolAddress((void**)&wph, g_wph); cudaGetSymbolAddress((void**)&wpl, g_wpl);

    cudaFuncSetAttribute(gemm_qkv, cudaFuncAttributeMaxDynamicSharedMemorySize, GEMM_SMEM);
    cudaFuncSetAttribute(gemm_o,   cudaFuncAttributeMaxDynamicSharedMemorySize, GEMM_SMEM);
    cudaFuncSetAttribute(attn_tc,  cudaFuncAttributeMaxDynamicSharedMemorySize, ATTN_SMEM);

    // 0) split weights into bf16 hi/lo
    auto split = [&](const float* s, __nv_bfloat16* hi, __nv_bfloat16* lo, size_t n) {
        const int n4 = (int)(n / 4);
        split_kernel<<<(n4 + 255) / 256, 256>>>((const float4*)s, (uint2*)hi, (uint2*)lo, n4);
    };
    split(wq,  wqh, wql, WQE);
    split(wkv, wkh, wkl, WKVE);
    split(wp,  wph, wpl, WQE);

    // 1) fused Q + KV projection (KV blocks first to avoid tail wave)
    gemm_qkv<<<KV_BLOCKS + Q_BLOCKS, 128, GEMM_SMEM>>>(x, cond, bq, bkv);

    // 2) Attention (tensor cores) -> g_attn
    {
        dim3 grid(NCTX / QR, NH, BSZ);                   // 32 x 16 x 8
        attn_tc<<<grid, 128, ATTN_SMEM>>>(mask);
    }
    // 3) Output projection -> d_out
    {
        dim3 grid(DM / 128, (BSZ * NCTX) / 128);         // 9 x 256
        gemm_o<<<grid, 128, GEMM_SMEM>>>(bp, out);
    }
}

// round 17
// speedup vs baseline: 1.8691x; 1.8691x over previous
#include <cuda_runtime.h>
#include <cuda_fp16.h>
#include <cstdint>

// ---------------------------------------------------------------------------
// Problem constants
// ---------------------------------------------------------------------------
constexpr int BSZ  = 8;
constexpr int NCTX = 4096;
constexpr int MCTX = 300;
constexpr int DM   = 1152;
constexpr int NH   = 16;
constexpr int HD   = 72;           // DM / NH
constexpr int MP   = 320;          // padded M for K^T / V scratch

constexpr size_t WQE  = (size_t)DM * DM;
constexpr size_t WKVE = (size_t)DM * 2 * DM;

// ---------------------------------------------------------------------------
// Scratch (device globals; zero-initialized, no allocations allowed)
// ---------------------------------------------------------------------------
__device__ float g_q   [(size_t)BSZ * NCTX * DM];          // [B,N,DM]
__device__ float g_attn[(size_t)BSZ * NCTX * DM];          // [B,N,DM]
__device__ float g_kT  [(size_t)BSZ * NH * HD * MP];       // [B,H,D,Mpad] (pads stay 0)
__device__ float g_v2  [(size_t)BSZ * NH * MP * 80];       // [B,H,Mpad,80] (pads stay 0)
__device__ __align__(16) __half g_wq16[WQE];               // plain fp16 weights
__device__ __align__(16) __half g_wk16[WKVE];
__device__ __align__(16) __half g_wp16[WQE];

// ---------------------------------------------------------------------------
// Helpers
// ---------------------------------------------------------------------------
__device__ __forceinline__ uint32_t smem_u32(const void* p) {
    uint32_t a;
    asm("{ .reg .u64 t; cvta.to.shared.u64 t, %1; cvt.u32.u64 %0, t; }"
        : "=r"(a) : "l"(p));
    return a;
}

__device__ __forceinline__ uint32_t pack_h2(__half a, __half b) {
    __half2 t = __halves2half2(a, b);
    return *reinterpret_cast<uint32_t*>(&t);
}

__device__ __forceinline__ void split_f16(float v, __half& h, __half& l) {
    h = __float2half_rn(v);
    l = __float2half_rn(v - __half2float(h));
}

__device__ __forceinline__ void cp16(uint32_t s, const void* g) {
    asm volatile("cp.async.cg.shared.global [%0], [%1], 16;"
                 :: "r"(s), "l"(g) : "memory");
}
#define CP_COMMIT()   asm volatile("cp.async.commit_group;" ::: "memory")
#define CP_WAIT(N)    asm volatile("cp.async.wait_group %0;" :: "n"(N) : "memory")

__device__ __forceinline__ void ldsm_x4(uint32_t& r0, uint32_t& r1,
                                        uint32_t& r2, uint32_t& r3, uint32_t a) {
    asm volatile("ldmatrix.sync.aligned.m8n8.x4.shared.b16 {%0,%1,%2,%3}, [%4];"
                 : "=r"(r0), "=r"(r1), "=r"(r2), "=r"(r3) : "r"(a));
}

__device__ __forceinline__ void ldsm_x4_t(uint32_t& r0, uint32_t& r1,
                                          uint32_t& r2, uint32_t& r3, uint32_t a) {
    asm volatile("ldmatrix.sync.aligned.m8n8.x4.trans.shared.b16 {%0,%1,%2,%3}, [%4];"
                 : "=r"(r0), "=r"(r1), "=r"(r2), "=r"(r3) : "r"(a));
}

__device__ __forceinline__ void mma16816(float* d, const uint32_t* a,
                                         uint32_t b0, uint32_t b1) {
    asm volatile(
        "mma.sync.aligned.m16n8k16.row.col.f32.f16.f16.f32 "
        "{%0,%1,%2,%3}, {%4,%5,%6,%7}, {%8,%9}, {%0,%1,%2,%3};"
        : "+f"(d[0]), "+f"(d[1]), "+f"(d[2]), "+f"(d[3])
        : "r"(a[0]), "r"(a[1]), "r"(a[2]), "r"(a[3]), "r"(b0), "r"(b1));
}

// ---------------------------------------------------------------------------
// Weight convert: fp32 -> plain fp16
// ---------------------------------------------------------------------------
__global__ void conv16_kernel(const float4* __restrict__ src,
                              uint2* __restrict__ dst, int n4)
{
    const int i = blockIdx.x * blockDim.x + threadIdx.x;
    if (i >= n4) return;
    float4 v = src[i];
    dst[i] = make_uint2(pack_h2(__float2half_rn(v.x), __float2half_rn(v.y)),
                        pack_h2(__float2half_rn(v.z), __float2half_rn(v.w)));
}

// ---------------------------------------------------------------------------
// fp16 split-2 GEMM: C = A(fp32, split Ah+Al) @ W(plain fp16) + bias
// CTA tile 128x128, BK=32, 4 warps (2x2 of 64x64), 128 threads, occ 2.
// MODE 0: row-major fp32 store. MODE 1: KV scatter into g_kT / g_v2.
// ---------------------------------------------------------------------------
constexpr int AS_STRIDE = 40;    // 32 + 8 pad (elems)
constexpr int BS_STRIDE = 136;   // 128 + 8 pad (elems)
constexpr int A_TILE_B  = 128 * AS_STRIDE * 2;   // 10240
constexpr int B_TILE_B  = 32  * BS_STRIDE * 2;   // 8704
constexpr int OFF_AH = 0;
constexpr int OFF_AL = OFF_AH + A_TILE_B;        // 10240
constexpr int OFF_BH = OFF_AL + A_TILE_B;        // 20480
constexpr int STAGE_B = OFF_BH + B_TILE_B;       // 29184
constexpr int GEMM_SMEM = 2 * STAGE_B;           // 58368

// coalesced B producer: 16 threads cover one 256B row; 8 rows per pass
__device__ __forceinline__ void produce_B(
    uint32_t st, int k0, int tid, int Nc, const __half* Bg)
{
    const int rbase = tid >> 4;          // 0..7
    const int ce    = (tid & 15) * 8;    // element offset (16B chunks)
    #pragma unroll
    for (int pass = 0; pass < 4; ++pass) {
        const int r = rbase + pass * 8;
        cp16(st + OFF_BH + (uint32_t)(r * BS_STRIDE + ce) * 2,
             Bg + (size_t)(k0 + r) * Nc + ce);
    }
    CP_COMMIT();
}

template <int MODE>
__global__ __launch_bounds__(128, 2)
void gemm_hmma(const float* __restrict__ A, const __half* __restrict__ Bg_,
               const float* __restrict__ bias, float* __restrict__ C,
               int Mr, int Nc, int Kd)
{
    extern __shared__ char dsm[];
    const uint32_t sbase = smem_u32(dsm);

    const int tid  = threadIdx.x;
    const int wid  = tid >> 5;
    const int lane = tid & 31;
    const int n0   = blockIdx.x * 128;
    const int m0   = blockIdx.y * 128;
    const int wm   = wid >> 1;
    const int wn   = wid & 1;

    const int arBase = tid >> 3;        // A producer: 16 rows/pass, 8 passes
    const int acol   = (tid & 7) * 4;
    const __half* Bg = Bg_ + n0;

    const int aFragRow = wm * 64 + (lane & 15);
    const int aFragCol = (lane >> 4) * 8;
    const int bFragRow = lane & 15;
    const int bFragCol = wn * 64 + (lane >> 4) * 8;

    float acc[4][8][4];
    #pragma unroll
    for (int i = 0; i < 4; i++)
        #pragma unroll
        for (int j = 0; j < 8; j++)
            #pragma unroll
            for (int e = 0; e < 4; e++) acc[i][j][e] = 0.0f;

    const int nchunks = Kd / 32;

    // ---- stage 0 ----
    produce_B(sbase, 0, tid, Nc, Bg);
    {
        char* pAH = dsm + OFF_AH;
        char* pAL = dsm + OFF_AL;
        #pragma unroll
        for (int it = 0; it < 8; ++it) {
            const int r = arBase + it * 16;
            int arow = m0 + r; if (arow >= Mr) arow = Mr - 1;
            float4 v = *(const float4*)(A + (size_t)arow * Kd + acol);
            __half h0, h1, h2, h3, l0, l1, l2, l3;
            split_f16(v.x, h0, l0); split_f16(v.y, h1, l1);
            split_f16(v.z, h2, l2); split_f16(v.w, h3, l3);
            const uint32_t off = (uint32_t)(r * AS_STRIDE + acol) * 2;
            *(uint2*)(pAH + off) = make_uint2(pack_h2(h0, h1), pack_h2(h2, h3));
            *(uint2*)(pAL + off) = make_uint2(pack_h2(l0, l1), pack_h2(l2, l3));
        }
    }
    CP_WAIT(0);
    __syncthreads();

    for (int c = 0; c < nchunks; ++c) {
        const int cur = c & 1;
        const int nb  = c + 1;
        const bool havenb = nb < nchunks;

        float4 pa[8];
        if (havenb) {
            produce_B(sbase + (nb & 1) * STAGE_B, nb * 32, tid, Nc, Bg);
            const int k0n = nb * 32;
            #pragma unroll
            for (int it = 0; it < 8; ++it) {
                const int r = arBase + it * 16;
                int arow = m0 + r; if (arow >= Mr) arow = Mr - 1;
                pa[it] = *(const float4*)(A + (size_t)arow * Kd + k0n + acol);
            }
        }

        const uint32_t st  = sbase + cur * STAGE_B;
        const uint32_t sAH = st + OFF_AH;
        const uint32_t sAL = st + OFF_AL;
        const uint32_t sBH = st + OFF_BH;

        #pragma unroll
        for (int kk = 0; kk < 32; kk += 16) {
            uint32_t Ah[4][4], Bh[4][4];
            #pragma unroll
            for (int mi = 0; mi < 4; ++mi) {
                uint32_t a = sAH + (uint32_t)((aFragRow + mi * 16) * AS_STRIDE
                                              + kk + aFragCol) * 2;
                ldsm_x4(Ah[mi][0], Ah[mi][1], Ah[mi][2], Ah[mi][3], a);
            }
            #pragma unroll
            for (int nj = 0; nj < 4; ++nj) {
                uint32_t boff = (uint32_t)((kk + bFragRow) * BS_STRIDE
                                           + bFragCol + nj * 16) * 2;
                ldsm_x4_t(Bh[nj][0], Bh[nj][1], Bh[nj][2], Bh[nj][3], sBH + boff);
            }
            // pass 1: Ah * W
            #pragma unroll
            for (int mi = 0; mi < 4; ++mi)
                #pragma unroll
                for (int nf = 0; nf < 8; ++nf) {
                    const int nj = nf >> 1, sub = (nf & 1) * 2;
                    mma16816(acc[mi][nf], Ah[mi], Bh[nj][sub], Bh[nj][sub + 1]);
                }
            // pass 2: Al * W
            uint32_t Al[4][4];
            #pragma unroll
            for (int mi = 0; mi < 4; ++mi) {
                uint32_t a = sAL + (uint32_t)((aFragRow + mi * 16) * AS_STRIDE
                                              + kk + aFragCol) * 2;
                ldsm_x4(Al[mi][0], Al[mi][1], Al[mi][2], Al[mi][3], a);
            }
            #pragma unroll
            for (int mi = 0; mi < 4; ++mi)
                #pragma unroll
                for (int nf = 0; nf < 8; ++nf) {
                    const int nj = nf >> 1, sub = (nf & 1) * 2;
                    mma16816(acc[mi][nf], Al[mi], Bh[nj][sub], Bh[nj][sub + 1]);
                }
        }

        if (havenb) {
            char* pAH = dsm + (nb & 1) * STAGE_B + OFF_AH;
            char* pAL = dsm + (nb & 1) * STAGE_B + OFF_AL;
            #pragma unroll
            for (int it = 0; it < 8; ++it) {
                const int r = arBase + it * 16;
                float4 v = pa[it];
                __half h0, h1, h2, h3, l0, l1, l2, l3;
                split_f16(v.x, h0, l0); split_f16(v.y, h1, l1);
                split_f16(v.z, h2, l2); split_f16(v.w, h3, l3);
                const uint32_t off = (uint32_t)(r * AS_STRIDE + acol) * 2;
                *(uint2*)(pAH + off) = make_uint2(pack_h2(h0, h1), pack_h2(h2, h3));
                *(uint2*)(pAL + off) = make_uint2(pack_h2(l0, l1), pack_h2(l2, l3));
            }
            CP_WAIT(0);
        }
        __syncthreads();
    }

    // ---------------- epilogue ----------------
    const int g = lane >> 2;
    const int t = lane & 3;
    #pragma unroll
    for (int mi = 0; mi < 4; ++mi) {
        #pragma unroll
        for (int half = 0; half < 2; ++half) {
            const int row = m0 + wm * 64 + mi * 16 + g + half * 8;
            if (row >= Mr) continue;
            #pragma unroll
            for (int nf = 0; nf < 8; ++nf) {
                const int col = n0 + wn * 64 + nf * 8 + 2 * t;
                float v0 = acc[mi][nf][half * 2 + 0] + bias[col];
                float v1 = acc[mi][nf][half * 2 + 1] + bias[col + 1];
                if (MODE == 0) {
                    *(float2*)(C + (size_t)row * Nc + col) = make_float2(v0, v1);
                } else {
                    const int b = row / MCTX, m = row - b * MCTX;
                    #pragma unroll
                    for (int e = 0; e < 2; ++e) {
                        int c2 = col + e;
                        const float val = e ? v1 : v0;
                        if (c2 < DM) {   // K: transposed [b,h,d,m]
                            const int h = c2 / HD, d = c2 - h * HD;
                            g_kT[((size_t)(b * NH + h) * HD + d) * MP + m] = val;
                        } else {         // V: [b,h,m,80]
                            c2 -= DM;
                            const int h = c2 / HD, d = c2 - h * HD;
                            g_v2[((size_t)(b * NH + h) * MP + m) * 80 + d] = val;
                        }
                    }
                }
            }
        }
    }
}

// ---------------------------------------------------------------------------
// Tensor-core attention (flash-style, no max subtraction — scores are O(1)).
// fp16 split-2: S = (Qh+Ql)*K (K plain), O = (Ph+Pl)*V (V plain).
// CTA = (b, h, 128 q-rows); 4 warps x 32 q-rows; M chunks of 64.
// ---------------------------------------------------------------------------
constexpr int QR   = 128;
constexpr int MC   = 64;
constexpr int QSTR = 88;
constexpr int KSTR = 72;
constexpr int VSTR = 88;
constexpr int OQH = 0;
constexpr int OQL = OQH + QR * QSTR * 2;        // 22528
constexpr int OKH = OQL + QR * QSTR * 2;        // 45056
constexpr int OVH = OKH + 80 * KSTR * 2;        // 56576
constexpr int ATTN_SMEM = OVH + MC * VSTR * 2;  // 67840

__global__ __launch_bounds__(128, 2)
void attn_tc(const int* __restrict__ mask, float* __restrict__ attn_out)
{
    extern __shared__ char dsm[];
    const uint32_t sbase = smem_u32(dsm);

    const int b   = blockIdx.z;
    const int h   = blockIdx.y;
    const int q0  = blockIdx.x * QR;
    const int tid = threadIdx.x;
    const int wid = tid >> 5;
    const int lane = tid & 31;
    const int g   = lane >> 2;
    const int t   = lane & 3;
    const int wq0 = wid * 32;
    const int mv  = mask[b];

    const float scale = rsqrtf((float)HD);

    // ---- produce Q tile (128 x 80; cols 72..79 zero), scale folded in ----
    {
        char* pQH = dsm + OQH;
        char* pQL = dsm + OQL;
        const float* qg = g_q + ((size_t)(b * NCTX) + q0) * DM + h * HD;
        for (int task = tid; task < QR * 18; task += 128) {
            const int r = task / 18, f4 = task - r * 18;
            float4 v = *(const float4*)(qg + (size_t)r * DM + f4 * 4);
            v.x *= scale; v.y *= scale; v.z *= scale; v.w *= scale;
            __half h0, h1, h2, h3, l0, l1, l2, l3;
            split_f16(v.x, h0, l0); split_f16(v.y, h1, l1);
            split_f16(v.z, h2, l2); split_f16(v.w, h3, l3);
            const uint32_t off = (uint32_t)(r * QSTR + f4 * 4) * 2;
            *(uint2*)(pQH + off) = make_uint2(pack_h2(h0, h1), pack_h2(h2, h3));
            *(uint2*)(pQL + off) = make_uint2(pack_h2(l0, l1), pack_h2(l2, l3));
        }
        // Q pad cols 72..79: one 16B store per row covers all 8 halves
        for (int task = tid; task < QR; task += 128) {
            const uint32_t off = (uint32_t)(task * QSTR + 72) * 2;
            *(uint4*)(dsm + OQH + off) = make_uint4(0u, 0u, 0u, 0u);
            *(uint4*)(dsm + OQL + off) = make_uint4(0u, 0u, 0u, 0u);
        }
        // K pad rows 72..79: FULL coverage — 9 x 16B chunks = 72 halves/row
        for (int task = tid; task < 8 * 9; task += 128) {
            const int d = 72 + task / 9, sg = task % 9;
            const uint32_t off = (uint32_t)(d * KSTR + sg * 8) * 2;
            *(uint4*)(dsm + OKH + off) = make_uint4(0u, 0u, 0u, 0u);
        }
    }

    float o[2][10][4];
    #pragma unroll
    for (int i = 0; i < 2; i++)
        #pragma unroll
        for (int j = 0; j < 10; j++)
            #pragma unroll
            for (int e = 0; e < 4; e++) o[i][j][e] = 0.0f;
    float rs[4] = {0.f, 0.f, 0.f, 0.f};

    for (int c0 = 0; c0 < mv; c0 += MC) {
        // ---- produce K^T tile (72 d-rows x 64 m-cols), plain fp16 ----
        {
            char* pKH = dsm + OKH;
            const float* kg = g_kT + (size_t)(b * NH + h) * HD * MP + c0;
            for (int task = tid; task < HD * 16; task += 128) {
                const int d = task >> 4, f4 = task & 15;
                float4 v = *(const float4*)(kg + (size_t)d * MP + f4 * 4);
                const uint32_t off = (uint32_t)(d * KSTR + f4 * 4) * 2;
                *(uint2*)(pKH + off) =
                    make_uint2(pack_h2(__float2half_rn(v.x), __float2half_rn(v.y)),
                               pack_h2(__float2half_rn(v.z), __float2half_rn(v.w)));
            }
        }
        // ---- produce V tile (64 m-rows x 80 d-cols), plain fp16 ----
        {
            char* pVH = dsm + OVH;
            const float* vg = g_v2 + ((size_t)(b * NH + h) * MP + c0) * 80;
            for (int task = tid; task < MC * 20; task += 128) {
                const int m = task / 20, f4 = task - m * 20;
                float4 v = *(const float4*)(vg + (size_t)m * 80 + f4 * 4);
                const uint32_t off = (uint32_t)(m * VSTR + f4 * 4) * 2;
                *(uint2*)(pVH + off) =
                    make_uint2(pack_h2(__float2half_rn(v.x), __float2half_rn(v.y)),
                               pack_h2(__float2half_rn(v.z), __float2half_rn(v.w)));
            }
        }
        __syncthreads();

        // ---- S = (Qh + Ql) @ K^T : 2 passes ----
        float S[2][8][4];
        #pragma unroll
        for (int i = 0; i < 2; i++)
            #pragma unroll
            for (int j = 0; j < 8; j++)
                #pragma unroll
                for (int e = 0; e < 4; e++) S[i][j][e] = 0.0f;

        #pragma unroll
        for (int kk = 0; kk < 5; ++kk) {
            uint32_t Ah[2][4], Al[2][4];
            #pragma unroll
            for (int mi = 0; mi < 2; ++mi) {
                const uint32_t aoff =
                    (uint32_t)((wq0 + mi * 16 + (lane & 15)) * QSTR
                               + kk * 16 + (lane >> 4) * 8) * 2;
                ldsm_x4(Ah[mi][0], Ah[mi][1], Ah[mi][2], Ah[mi][3], sbase + OQH + aoff);
                ldsm_x4(Al[mi][0], Al[mi][1], Al[mi][2], Al[mi][3], sbase + OQL + aoff);
            }
            #pragma unroll
            for (int nj = 0; nj < 4; ++nj) {
                uint32_t Bh[4];
                const uint32_t boff =
                    (uint32_t)((kk * 16 + (lane & 15)) * KSTR
                               + nj * 16 + (lane >> 4) * 8) * 2;
                ldsm_x4_t(Bh[0], Bh[1], Bh[2], Bh[3], sbase + OKH + boff);
                #pragma unroll
                for (int mi = 0; mi < 2; ++mi) {
                    mma16816(S[mi][2 * nj + 0], Ah[mi], Bh[0], Bh[1]);
                    mma16816(S[mi][2 * nj + 1], Ah[mi], Bh[2], Bh[3]);
                    mma16816(S[mi][2 * nj + 0], Al[mi], Bh[0], Bh[1]);
                    mma16816(S[mi][2 * nj + 1], Al[mi], Bh[2], Bh[3]);
                }
            }
        }

        // ---- p = exp(s); accumulate row sums ----
        if (c0 + MC <= mv) {
            #pragma unroll
            for (int mi = 0; mi < 2; ++mi)
                #pragma unroll
                for (int nf = 0; nf < 8; ++nf)
                    #pragma unroll
                    for (int e = 0; e < 4; ++e) {
                        const float p = __expf(S[mi][nf][e]);
                        S[mi][nf][e] = p;
                        rs[mi * 2 + (e >> 1)] += p;
                    }
        } else {
            #pragma unroll
            for (int mi = 0; mi < 2; ++mi)
                #pragma unroll
                for (int nf = 0; nf < 8; ++nf)
                    #pragma unroll
                    for (int e = 0; e < 4; ++e) {
                        const int col = c0 + nf * 8 + 2 * t + (e & 1);
                        const float p = (col < mv) ? __expf(S[mi][nf][e]) : 0.0f;
                        S[mi][nf][e] = p;
                        rs[mi * 2 + (e >> 1)] += p;
                    }
        }

        // ---- O += (Ph + Pl) @ V : 2 passes ----
        #pragma unroll
        for (int kk2 = 0; kk2 < 4; ++kk2) {
            uint32_t Ph[2][4], Pl[2][4];
            #pragma unroll
            for (int mi = 0; mi < 2; ++mi) {
                const int nfa = 2 * kk2, nfb = nfa + 1;
                __half hh, ll;
                uint32_t hp[8], lp[8];
                #pragma unroll
                for (int e = 0; e < 4; ++e) {
                    split_f16(S[mi][nfa][e], hh, ll);
                    hp[e] = (uint32_t)*(uint16_t*)&hh;
                    lp[e] = (uint32_t)*(uint16_t*)&ll;
                    split_f16(S[mi][nfb][e], hh, ll);
                    hp[4 + e] = (uint32_t)*(uint16_t*)&hh;
                    lp[4 + e] = (uint32_t)*(uint16_t*)&ll;
                }
                Ph[mi][0] = hp[0] | (hp[1] << 16);
                Ph[mi][1] = hp[2] | (hp[3] << 16);
                Ph[mi][2] = hp[4] | (hp[5] << 16);
                Ph[mi][3] = hp[6] | (hp[7] << 16);
                Pl[mi][0] = lp[0] | (lp[1] << 16);
                Pl[mi][1] = lp[2] | (lp[3] << 16);
                Pl[mi][2] = lp[4] | (lp[5] << 16);
                Pl[mi][3] = lp[6] | (lp[7] << 16);
            }
            #pragma unroll
            for (int vt = 0; vt < 5; ++vt) {
                uint32_t Vh[4];
                const uint32_t voff =
                    (uint32_t)((kk2 * 16 + (lane & 15)) * VSTR
                               + vt * 16 + (lane >> 4) * 8) * 2;
                ldsm_x4_t(Vh[0], Vh[1], Vh[2], Vh[3], sbase + OVH + voff);
                #pragma unroll
                for (int mi = 0; mi < 2; ++mi) {
                    mma16816(o[mi][2 * vt + 0], Ph[mi], Vh[0], Vh[1]);
                    mma16816(o[mi][2 * vt + 1], Ph[mi], Vh[2], Vh[3]);
                    mma16816(o[mi][2 * vt + 0], Pl[mi], Vh[0], Vh[1]);
                    mma16816(o[mi][2 * vt + 1], Pl[mi], Vh[2], Vh[3]);
                }
            }
        }
        __syncthreads();
    }

    // ---- finalize: reduce row sums across the quad, scale, store ----
    #pragma unroll
    for (int i = 0; i < 4; ++i) {
        rs[i] += __shfl_xor_sync(0xFFFFFFFFu, rs[i], 1);
        rs[i] += __shfl_xor_sync(0xFFFFFFFFu, rs[i], 2);
        rs[i] = 1.0f / rs[i];
    }

    float* op = attn_out + (size_t)(b * NCTX) * DM + h * HD;
    #pragma unroll
    for (int mi = 0; mi < 2; ++mi)
        #pragma unroll
        for (int half = 0; half < 2; ++half) {
            const int row = q0 + wq0 + mi * 16 + g + half * 8;
            const float inv = rs[mi * 2 + half];
            #pragma unroll
            for (int nt = 0; nt < 9; ++nt) {
                const int col = nt * 8 + 2 * t;
                float2 v;
                v.x = o[mi][nt][half * 2 + 0] * inv;
                v.y = o[mi][nt][half * 2 + 1] * inv;
                *(float2*)(op + (size_t)row * DM + col) = v;
            }
        }
}

// ---------------------------------------------------------------------------
// Launch
// ---------------------------------------------------------------------------
extern "C" void kernel_launch(void* const* d_in, const int* in_sizes, int n_in,
                              void* d_out, int out_size)
{
    (void)in_sizes; (void)n_in; (void)out_size;
    const float* x    = (const float*)d_in[0];
    const float* cond = (const float*)d_in[1];
    const int*   mask = (const int*)  d_in[2];
    const float* wq   = (const float*)d_in[3];
    const float* bq   = (const float*)d_in[4];
    const float* wkv  = (const float*)d_in[5];
    const float* bkv  = (const float*)d_in[6];
    const float* wp   = (const float*)d_in[7];
    const float* bp   = (const float*)d_in[8];
    float* out        = (float*)d_out;

    float *qptr = nullptr, *attnptr = nullptr;
    cudaGetSymbolAddress((void**)&qptr,    g_q);
    cudaGetSymbolAddress((void**)&attnptr, g_attn);
    __half *wq16, *wk16, *wp16;
    cudaGetSymbolAddress((void**)&wq16, g_wq16);
    cudaGetSymbolAddress((void**)&wk16, g_wk16);
    cudaGetSymbolAddress((void**)&wp16, g_wp16);

    cudaFuncSetAttribute(gemm_hmma<0>,
                         cudaFuncAttributeMaxDynamicSharedMemorySize, GEMM_SMEM);
    cudaFuncSetAttribute(gemm_hmma<1>,
                         cudaFuncAttributeMaxDynamicSharedMemorySize, GEMM_SMEM);
    cudaFuncSetAttribute(attn_tc,
                         cudaFuncAttributeMaxDynamicSharedMemorySize, ATTN_SMEM);

    // 0) convert weights to plain fp16
    auto conv = [&](const float* s, __half* d, size_t n) {
        const int n4 = (int)(n / 4);
        conv16_kernel<<<(n4 + 255) / 256, 256>>>((const float4*)s, (uint2*)d, n4);
    };
    conv(wq,  wq16, WQE);
    conv(wkv, wk16, WKVE);
    conv(wp,  wp16, WQE);

    const int rowsA  = BSZ * NCTX;   // 32768
    const int rowsKV = BSZ * MCTX;   // 2400

    // 1) KV projection + transposed scatter
    {
        dim3 grid(2 * DM / 128, (rowsKV + 127) / 128);   // 18 x 19
        gemm_hmma<1><<<grid, 128, GEMM_SMEM>>>(cond, wk16, bkv, nullptr,
                                               rowsKV, 2 * DM, DM);
    }
    // 2) Q projection
    {
        dim3 grid(DM / 128, rowsA / 128);                // 9 x 256
        gemm_hmma<0><<<grid, 128, GEMM_SMEM>>>(x, wq16, bq, qptr,
                                               rowsA, DM, DM);
    }
    // 3) Attention (tensor cores)
    {
        dim3 grid(NCTX / QR, NH, BSZ);                   // 32 x 16 x 8
        attn_tc<<<grid, 128, ATTN_SMEM>>>(mask, attnptr);
    }
    // 4) Output projection
    {
        dim3 grid(DM / 128, rowsA / 128);
        gemm_hmma<0><<<grid, 128, GEMM_SMEM>>>(attnptr, wp16, bp, out,
                                               rowsA, DM, DM);
    }
}